// round 1
// baseline (speedup 1.0000x reference)
#include <cuda_runtime.h>
#include <math.h>
#include <stdint.h>

// Problem constants
#define Bb 32
#define Tt 64
#define Ee 64
#define Uu 32
#define D0 300
#define D1 100
#define Ss 9
#define CELL 64
#define Cc 6
#define ROWS (Bb*Tt)      // 2048
#define G4E (4*Ee)        // 256

// Device scratch (no allocation allowed)
__device__ float g_xproj0[ROWS * G4E];
__device__ float g_xproj1[ROWS * G4E];
__device__ float g_h0[ROWS * Ee];
__device__ float g_h1[ROWS * Ee];
__device__ float g_krT[Ee * Uu];   // [e][u]
__device__ float g_kiT[Ee * Uu];

// ---------------------------------------------------------------------------
// Kernel 0: normalize measurement kernel, store transposed
// ---------------------------------------------------------------------------
__global__ void prep_kernel(const float* __restrict__ mk) {
    __shared__ float inv_norm[Uu];
    int tid = threadIdx.x;               // 256 threads
    if (tid < Uu) {
        float s = 0.f;
        const float* p = mk + tid * (Ee * 2);
        #pragma unroll 8
        for (int i = 0; i < Ee * 2; i++) s += p[i] * p[i];
        float n = sqrtf(s);
        n = fmaxf(n, 1e-12f);
        inv_norm[tid] = 1.f / n;
    }
    __syncthreads();
    // 2048 (u,e) pairs
    for (int idx = tid; idx < Uu * Ee; idx += blockDim.x) {
        int u = idx >> 6;
        int e = idx & 63;
        float inv = inv_norm[u];
        g_krT[e * Uu + u] = mk[(u * Ee + e) * 2 + 0] * inv;
        g_kiT[e * Uu + u] = mk[(u * Ee + e) * 2 + 1] * inv;
    }
}

// ---------------------------------------------------------------------------
// Kernel 1: input projection GEMM
// out[m][n] = umask[m] * sum_k A[m][k]*W[n][k] + bih[n] + bhh[n]
// M=2048, N=256, K in {300,100}. grid = (N/64, M/64), 256 threads.
// ---------------------------------------------------------------------------
#define BKK 16
__global__ void gemm_xproj(const float* __restrict__ A, const float* __restrict__ W,
                           const float* __restrict__ bih, const float* __restrict__ bhh,
                           const float* __restrict__ umask, float* __restrict__ out,
                           int K) {
    __shared__ float As[BKK][64];
    __shared__ float Ws[BKK][64];
    int tid = threadIdx.x;
    int tx = tid & 15, ty = tid >> 4;
    int bm = blockIdx.y * 64, bn = blockIdx.x * 64;
    float acc[4][4] = {};
    int a_m = tid >> 2;          // 0..63
    int a_k = (tid & 3) * 4;     // 0,4,8,12

    for (int k0 = 0; k0 < K; k0 += BKK) {
        #pragma unroll
        for (int i = 0; i < 4; i++) {
            int k = k0 + a_k + i;
            As[a_k + i][a_m] = (k < K) ? A[(size_t)(bm + a_m) * K + k] : 0.f;
            Ws[a_k + i][a_m] = (k < K) ? W[(size_t)(bn + a_m) * K + k] : 0.f;
        }
        __syncthreads();
        #pragma unroll
        for (int kk = 0; kk < BKK; kk++) {
            float4 av = *(const float4*)&As[kk][ty * 4];
            float4 wv = *(const float4*)&Ws[kk][tx * 4];
            float a[4] = {av.x, av.y, av.z, av.w};
            float w[4] = {wv.x, wv.y, wv.z, wv.w};
            #pragma unroll
            for (int i = 0; i < 4; i++)
                #pragma unroll
                for (int j = 0; j < 4; j++)
                    acc[i][j] += a[i] * w[j];
        }
        __syncthreads();
    }
    #pragma unroll
    for (int i = 0; i < 4; i++) {
        int m = bm + ty * 4 + i;
        float um = umask[m];
        #pragma unroll
        for (int j = 0; j < 4; j++) {
            int n = bn + tx * 4 + j;
            out[(size_t)m * G4E + n] = um * acc[i][j] + bih[n] + bhh[n];
        }
    }
}

// ---------------------------------------------------------------------------
// Kernel 2: sequential LSTM recurrence with extra tanh on h.
// 64 blocks: blockIdx = mod*32 + b.  256 threads = one per gate row.
// Whh row held in registers; h broadcast via smem float4.
// ---------------------------------------------------------------------------
__device__ __forceinline__ float sigf(float x) { return 1.f / (1.f + expf(-x)); }

__global__ void lstm_kernel(const float* __restrict__ Whh0, const float* __restrict__ Whh1) {
    int mod = blockIdx.x >> 5;
    int b = blockIdx.x & 31;
    const float* Whh = mod ? Whh1 : Whh0;
    const float* xp = (mod ? g_xproj1 : g_xproj0) + (size_t)b * Tt * G4E;
    float* hout = (mod ? g_h1 : g_h0) + (size_t)b * Tt * Ee;
    int j = threadIdx.x;   // 0..255

    float w[Ee];
    #pragma unroll
    for (int e = 0; e < Ee; e++) w[e] = Whh[j * Ee + e];

    __shared__ float4 h4[Ee / 4];
    __shared__ float gs[G4E];
    float* hs = (float*)h4;
    float c = 0.f;
    if (j < Ee) hs[j] = 0.f;
    __syncthreads();

    for (int t = 0; t < Tt; t++) {
        float g = xp[t * G4E + j];
        float a0 = 0.f, a1 = 0.f, a2 = 0.f, a3 = 0.f;
        #pragma unroll
        for (int e4 = 0; e4 < Ee / 4; e4++) {
            float4 h = h4[e4];
            a0 += w[e4 * 4 + 0] * h.x;
            a1 += w[e4 * 4 + 1] * h.y;
            a2 += w[e4 * 4 + 2] * h.z;
            a3 += w[e4 * 4 + 3] * h.w;
        }
        g += (a0 + a1) + (a2 + a3);
        // gate nonlinearity, all 256 threads in parallel
        int gi = j >> 6;                 // 0:i 1:f 2:g 3:o
        float act = (gi == 2) ? tanhf(g) : sigf(g);
        gs[j] = act;
        __syncthreads();
        if (j < Ee) {
            float ai = gs[j], af = gs[Ee + j], ag = gs[2 * Ee + j], ao = gs[3 * Ee + j];
            c = af * c + ai * ag;
            float h = tanhf(ao * tanhf(c));
            hs[j] = h;
            hout[t * Ee + j] = h;
        }
        __syncthreads();
    }
}

// ---------------------------------------------------------------------------
// Kernel 3: normalize + phase + measurement + MLP + log_softmax.
// 512 blocks x 256 threads; 4 rows per block (slot = tid/64).
// ---------------------------------------------------------------------------
__global__ void epilogue_kernel(const float* __restrict__ smask,
                                const float* __restrict__ phase_table,
                                const float* __restrict__ W1, const float* __restrict__ b1,
                                const float* __restrict__ W2, const float* __restrict__ b2,
                                float* __restrict__ out) {
    __shared__ float krT[Ee * Uu];          // 8KB
    __shared__ float kiT[Ee * Uu];          // 8KB
    __shared__ float W1s[CELL * 65];        // padded rows, ~16.6KB
    __shared__ float r0s[4][Ee], i0s[4][Ee], r1s[4][Ee], i1s[4][Ee];
    __shared__ float ms[4][2 * Uu];
    __shared__ float hids[4][CELL];
    __shared__ float preds[4][8];
    __shared__ float part[4][2][2];
    __shared__ int   sidx[4];
    __shared__ float lse_s[4];

    int tid = threadIdx.x;
    int slot = tid >> 6;
    int lt = tid & 63;
    int row = blockIdx.x * 4 + slot;

    // load shared weights (coalesced)
    for (int i = tid; i < Ee * Uu; i += 256) { krT[i] = g_krT[i]; kiT[i] = g_kiT[i]; }
    for (int i = tid; i < CELL * CELL; i += 256) {
        int cc = i >> 6, k = i & 63;
        W1s[cc * 65 + k] = W1[i];
    }

    // load h, compute norms
    float h0 = g_h0[row * Ee + lt];
    float h1 = g_h1[row * Ee + lt];
    float v0 = h0 * h0, v1 = h1 * h1;
    #pragma unroll
    for (int off = 16; off; off >>= 1) {
        v0 += __shfl_xor_sync(0xffffffffu, v0, off);
        v1 += __shfl_xor_sync(0xffffffffu, v1, off);
    }
    if ((tid & 31) == 0) { part[slot][lt >> 5][0] = v0; part[slot][lt >> 5][1] = v1; }
    if (lt == 0) {
        // argmax over smask (first max wins)
        const float* sm = smask + row * Ss;
        float best = sm[0]; int bi = 0;
        #pragma unroll
        for (int e = 1; e < Ss; e++) { float v = sm[e]; if (v > best) { best = v; bi = e; } }
        sidx[slot] = bi;
    }
    __syncthreads();

    float s0 = part[slot][0][0] + part[slot][1][0];
    float s1 = part[slot][0][1] + part[slot][1][1];
    float inv0 = 1.f / fmaxf(sqrtf(s0), 1e-12f);
    float inv1 = 1.f / fmaxf(sqrtf(s1), 1e-12f);
    float n0 = h0 * inv0, n1 = h1 * inv1;

    float ph = phase_table[sidx[slot] * Ee + lt];
    float cp = cosf(ph), sp = sinf(ph);
    r0s[slot][lt] = cp * n0;  i0s[slot][lt] = sp * n0;
    r1s[slot][lt] = cp * n1;  i1s[slot][lt] = sp * n1;
    __syncthreads();

    // measurement: thread lt = u index into concat output (0..31 mod0, 32..63 mod1)
    {
        int mod = lt >> 5;
        int uu = lt & 31;     // == lane id within warp
        const float* R = mod ? r1s[slot] : r0s[slot];
        const float* I = mod ? i1s[slot] : i0s[slot];
        float pr = 0.f, pi = 0.f;
        #pragma unroll 16
        for (int e = 0; e < Ee; e++) {
            float kr = krT[e * Uu + uu];
            float ki = kiT[e * Uu + uu];
            float r = R[e], im = I[e];
            pr += kr * r - ki * im;
            pi += ki * r + kr * im;
        }
        ms[slot][lt] = pr * pr + pi * pi;
    }
    __syncthreads();

    // MLP layer 1: hid[c] = relu(sum_k m[k]*W1[c][k] + b1[c])
    {
        int cc = lt;
        float acc = b1[cc];
        #pragma unroll 16
        for (int k = 0; k < CELL; k++) acc += ms[slot][k] * W1s[cc * 65 + k];
        hids[slot][cc] = fmaxf(acc, 0.f);
    }
    __syncthreads();

    // MLP layer 2 + tanh
    if (lt < Cc) {
        float acc = b2[lt];
        const float* w2 = W2 + lt * CELL;
        #pragma unroll 16
        for (int k = 0; k < CELL; k++) acc += hids[slot][k] * w2[k];
        preds[slot][lt] = tanhf(acc);
    }
    __syncthreads();

    if (lt == 0) {
        float m = preds[slot][0];
        #pragma unroll
        for (int k = 1; k < Cc; k++) m = fmaxf(m, preds[slot][k]);
        float se = 0.f;
        #pragma unroll
        for (int k = 0; k < Cc; k++) se += expf(preds[slot][k] - m);
        lse_s[slot] = m + logf(se);
    }
    __syncthreads();

    if (lt < Cc) out[row * Cc + lt] = preds[slot][lt] - lse_s[slot];
}

// ---------------------------------------------------------------------------
extern "C" void kernel_launch(void* const* d_in, const int* in_sizes, int n_in,
                              void* d_out, int out_size) {
    const float* x0        = (const float*)d_in[0];
    const float* x1        = (const float*)d_in[1];
    const float* smask     = (const float*)d_in[2];
    const float* umask     = (const float*)d_in[3];
    const float* W_ih0     = (const float*)d_in[4];
    const float* W_hh0     = (const float*)d_in[5];
    const float* b_ih0     = (const float*)d_in[6];
    const float* b_hh0     = (const float*)d_in[7];
    const float* W_ih1     = (const float*)d_in[8];
    const float* W_hh1     = (const float*)d_in[9];
    const float* b_ih1     = (const float*)d_in[10];
    const float* b_hh1     = (const float*)d_in[11];
    const float* phase_tab = (const float*)d_in[12];
    const float* meas_k    = (const float*)d_in[13];
    const float* W1        = (const float*)d_in[14];
    const float* b1        = (const float*)d_in[15];
    const float* W2        = (const float*)d_in[16];
    const float* b2        = (const float*)d_in[17];
    float* out = (float*)d_out;

    float* xp0; cudaGetSymbolAddress((void**)&xp0, g_xproj0);
    float* xp1; cudaGetSymbolAddress((void**)&xp1, g_xproj1);

    prep_kernel<<<1, 256>>>(meas_k);

    dim3 ggrid(G4E / 64, ROWS / 64);
    gemm_xproj<<<ggrid, 256>>>(x0, W_ih0, b_ih0, b_hh0, umask, xp0, D0);
    gemm_xproj<<<ggrid, 256>>>(x1, W_ih1, b_ih1, b_hh1, umask, xp1, D1);

    lstm_kernel<<<64, 256>>>(W_hh0, W_hh1);

    epilogue_kernel<<<ROWS / 4, 256>>>(smask, phase_tab, W1, b1, W2, b2, out);
}

// round 2
// speedup vs baseline: 1.0665x; 1.0665x over previous
#include <cuda_runtime.h>
#include <math.h>
#include <stdint.h>

// Problem constants
#define Bb 32
#define Tt 64
#define Ee 64
#define Uu 32
#define D0 300
#define D1 100
#define Ss 9
#define CELL 64
#define Cc 6
#define ROWS (Bb*Tt)      // 2048
#define G4E (4*Ee)        // 256

// Device scratch
__device__ float g_xproj0[ROWS * G4E];
__device__ float g_xproj1[ROWS * G4E];
__device__ float g_h0[ROWS * Ee];
__device__ float g_h1[ROWS * Ee];
__device__ float g_krT[Ee * Uu];   // [e][u]
__device__ float g_kiT[Ee * Uu];

// ---------------------------------------------------------------------------
// fast activations (MUFU-based, clamped for safety)
// ---------------------------------------------------------------------------
__device__ __forceinline__ float fsig(float x) {
    x = fminf(fmaxf(x, -30.f), 30.f);
    return __fdividef(1.f, 1.f + __expf(-x));
}
__device__ __forceinline__ float ftanh_(float x) {
    x = fminf(fmaxf(x, -15.f), 15.f);
    float e = __expf(2.f * x);
    return 1.f - __fdividef(2.f, e + 1.f);
}

// packed f32x2 helpers (Blackwell)
__device__ __forceinline__ unsigned long long ffma2(unsigned long long a,
                                                    unsigned long long b,
                                                    unsigned long long c) {
    unsigned long long d;
    asm("fma.rn.f32x2 %0, %1, %2, %3;" : "=l"(d) : "l"(a), "l"(b), "l"(c));
    return d;
}
__device__ __forceinline__ unsigned long long fadd2(unsigned long long a,
                                                    unsigned long long b) {
    unsigned long long d;
    asm("add.rn.f32x2 %0, %1, %2;" : "=l"(d) : "l"(a), "l"(b));
    return d;
}

// ---------------------------------------------------------------------------
// Kernel 1: merged input-projection GEMM (both modalities) + prep slice.
// grid = (5, 32, 2): x in [0,4) -> N tiles; x==4,y==0,z==0 -> prep.
// out[m][n] = umask[m]*sum_k A[m][k]*W[n][k] + bih[n] + bhh[n]
// ---------------------------------------------------------------------------
#define BKK 16
__global__ void __launch_bounds__(256) gemm_xproj(
    const float* __restrict__ x0, const float* __restrict__ Wih0,
    const float* __restrict__ bih0, const float* __restrict__ bhh0,
    const float* __restrict__ x1, const float* __restrict__ Wih1,
    const float* __restrict__ bih1, const float* __restrict__ bhh1,
    const float* __restrict__ umask, const float* __restrict__ mk) {

    if (blockIdx.x == 4) {
        if (blockIdx.y != 0 || blockIdx.z != 0) return;
        // prep: normalize measurement kernel, store transposed
        __shared__ float inv_norm[Uu];
        int tid = threadIdx.x;
        if (tid < Uu) {
            float s = 0.f;
            const float* p = mk + tid * (Ee * 2);
            #pragma unroll 8
            for (int i = 0; i < Ee * 2; i++) s += p[i] * p[i];
            inv_norm[tid] = 1.f / fmaxf(sqrtf(s), 1e-12f);
        }
        __syncthreads();
        for (int idx = tid; idx < Uu * Ee; idx += blockDim.x) {
            int u = idx >> 6;
            int e = idx & 63;
            float inv = inv_norm[u];
            g_krT[e * Uu + u] = mk[(u * Ee + e) * 2 + 0] * inv;
            g_kiT[e * Uu + u] = mk[(u * Ee + e) * 2 + 1] * inv;
        }
        return;
    }

    int mod = blockIdx.z;
    const float* A   = mod ? x1 : x0;
    const float* W   = mod ? Wih1 : Wih0;
    const float* bih = mod ? bih1 : bih0;
    const float* bhh = mod ? bhh1 : bhh0;
    float* out = mod ? g_xproj1 : g_xproj0;
    int K = mod ? D1 : D0;

    __shared__ float As[BKK][64];
    __shared__ float Ws[BKK][64];
    int tid = threadIdx.x;
    int tx = tid & 15, ty = tid >> 4;
    int bm = blockIdx.y * 64, bn = blockIdx.x * 64;
    float acc[4][4] = {};
    int a_m = tid >> 2;
    int a_k = (tid & 3) * 4;

    for (int k0 = 0; k0 < K; k0 += BKK) {
        #pragma unroll
        for (int i = 0; i < 4; i++) {
            int k = k0 + a_k + i;
            As[a_k + i][a_m] = (k < K) ? A[(size_t)(bm + a_m) * K + k] : 0.f;
            Ws[a_k + i][a_m] = (k < K) ? W[(size_t)(bn + a_m) * K + k] : 0.f;
        }
        __syncthreads();
        #pragma unroll
        for (int kk = 0; kk < BKK; kk++) {
            float4 av = *(const float4*)&As[kk][ty * 4];
            float4 wv = *(const float4*)&Ws[kk][tx * 4];
            float a[4] = {av.x, av.y, av.z, av.w};
            float w[4] = {wv.x, wv.y, wv.z, wv.w};
            #pragma unroll
            for (int i = 0; i < 4; i++)
                #pragma unroll
                for (int j = 0; j < 4; j++)
                    acc[i][j] += a[i] * w[j];
        }
        __syncthreads();
    }
    #pragma unroll
    for (int i = 0; i < 4; i++) {
        int m = bm + ty * 4 + i;
        float um = umask[m];
        #pragma unroll
        for (int j = 0; j < 4; j++) {
            int n = bn + tx * 4 + j;
            out[(size_t)m * G4E + n] = um * acc[i][j] + bih[n] + bhh[n];
        }
    }
}

// ---------------------------------------------------------------------------
// Kernel 2: LSTM recurrence.
// 64 blocks (mod*32+b), 256 threads.
// thread layout: warp w, lane l; gate gt = l&3, cell = w*8 + (l>>2).
// Each thread computes gate row r = gt*64+cell dot h (packed f32x2).
// 3 SHFL.BFLY gather the 4 activations; gt==0 lane does the cell update.
// Double-buffered h in smem -> single barrier per step. xp prefetched.
// ---------------------------------------------------------------------------
__global__ void __launch_bounds__(256, 1) lstm_kernel(
    const float* __restrict__ Whh0, const float* __restrict__ Whh1) {
    int mod = blockIdx.x >> 5;
    int b = blockIdx.x & 31;
    const float* Whh = mod ? Whh1 : Whh0;
    const float* xp = (mod ? g_xproj1 : g_xproj0) + (size_t)b * Tt * G4E;
    float* hout = (mod ? g_h1 : g_h0) + (size_t)b * Tt * Ee;

    int tid = threadIdx.x;
    int w = tid >> 5, l = tid & 31;
    int gt = l & 3;
    int cell = w * 8 + (l >> 2);
    int r = gt * 64 + cell;

    // Whh row r into packed registers (32 x f32x2)
    unsigned long long wp[32];
    {
        const float2* src = (const float2*)(Whh + (size_t)r * Ee);
        #pragma unroll
        for (int i = 0; i < 32; i++) {
            union { float2 f; unsigned long long u; } cv;
            cv.f = src[i];
            wp[i] = cv.u;
        }
    }

    __shared__ __align__(16) float hs[2][Ee];
    if (tid < Ee) hs[0][tid] = 0.f;
    float c = 0.f;
    __syncthreads();

    float gpre = xp[r];
    #pragma unroll 1
    for (int t = 0; t < Tt; t++) {
        float gnext = (t + 1 < Tt) ? xp[(t + 1) * G4E + r] : 0.f;  // prefetch

        const ulonglong2* h2 = (const ulonglong2*)hs[t & 1];
        unsigned long long a0 = 0ull, a1 = 0ull, a2 = 0ull, a3 = 0ull;
        #pragma unroll
        for (int i = 0; i < 16; i += 2) {
            ulonglong2 hv = h2[i];
            a0 = ffma2(wp[2 * i + 0], hv.x, a0);
            a1 = ffma2(wp[2 * i + 1], hv.y, a1);
            ulonglong2 hv2 = h2[i + 1];
            a2 = ffma2(wp[2 * i + 2], hv2.x, a2);
            a3 = ffma2(wp[2 * i + 3], hv2.y, a3);
        }
        unsigned long long s = fadd2(fadd2(a0, a1), fadd2(a2, a3));
        float lo, hi;
        asm("mov.b64 {%0,%1}, %2;" : "=f"(lo), "=f"(hi) : "l"(s));
        float g = gpre + lo + hi;
        gpre = gnext;

        // activation: i,f,o -> sigmoid; g -> tanh
        float act = (gt == 2) ? ftanh_(g) : fsig(g);

        // gather 4 activations within the 4-lane group
        float v1 = __shfl_xor_sync(0xffffffffu, act, 1);
        float v2 = __shfl_xor_sync(0xffffffffu, act, 2);
        float v3 = __shfl_xor_sync(0xffffffffu, v1, 2);

        if (gt == 0) {
            // act = sig(i), v1 = sig(f), v2 = tanh(g), v3 = sig(o)
            c = v1 * c + act * v2;
            float h = ftanh_(v3 * ftanh_(c));
            hs[(t + 1) & 1][cell] = h;
            hout[t * Ee + cell] = h;
        }
        __syncthreads();
    }
}

// ---------------------------------------------------------------------------
// Kernel 3: normalize + phase + measurement + MLP + log_softmax.
// ---------------------------------------------------------------------------
__global__ void __launch_bounds__(256) epilogue_kernel(
    const float* __restrict__ smask, const float* __restrict__ phase_table,
    const float* __restrict__ W1, const float* __restrict__ b1,
    const float* __restrict__ W2, const float* __restrict__ b2,
    float* __restrict__ out) {
    __shared__ float krT[Ee * Uu];
    __shared__ float kiT[Ee * Uu];
    __shared__ float W1s[CELL * 65];
    __shared__ float r0s[4][Ee], i0s[4][Ee], r1s[4][Ee], i1s[4][Ee];
    __shared__ float ms[4][2 * Uu];
    __shared__ float hids[4][CELL];
    __shared__ float preds[4][8];
    __shared__ float part[4][2][2];
    __shared__ int sidx[4];
    __shared__ float lse_s[4];

    int tid = threadIdx.x;
    int slot = tid >> 6;
    int lt = tid & 63;
    int row = blockIdx.x * 4 + slot;

    for (int i = tid; i < Ee * Uu; i += 256) { krT[i] = g_krT[i]; kiT[i] = g_kiT[i]; }
    for (int i = tid; i < CELL * CELL; i += 256) {
        int cc = i >> 6, k = i & 63;
        W1s[cc * 65 + k] = W1[i];
    }

    float h0 = g_h0[row * Ee + lt];
    float h1 = g_h1[row * Ee + lt];
    float v0 = h0 * h0, v1 = h1 * h1;
    #pragma unroll
    for (int off = 16; off; off >>= 1) {
        v0 += __shfl_xor_sync(0xffffffffu, v0, off);
        v1 += __shfl_xor_sync(0xffffffffu, v1, off);
    }
    if ((tid & 31) == 0) { part[slot][lt >> 5][0] = v0; part[slot][lt >> 5][1] = v1; }
    if (lt == 0) {
        const float* sm = smask + row * Ss;
        float best = sm[0]; int bi = 0;
        #pragma unroll
        for (int e = 1; e < Ss; e++) { float v = sm[e]; if (v > best) { best = v; bi = e; } }
        sidx[slot] = bi;
    }
    __syncthreads();

    float s0 = part[slot][0][0] + part[slot][1][0];
    float s1 = part[slot][0][1] + part[slot][1][1];
    float inv0 = 1.f / fmaxf(sqrtf(s0), 1e-12f);
    float inv1 = 1.f / fmaxf(sqrtf(s1), 1e-12f);
    float n0 = h0 * inv0, n1 = h1 * inv1;

    float ph = phase_table[sidx[slot] * Ee + lt];
    float cp = cosf(ph), sp = sinf(ph);
    r0s[slot][lt] = cp * n0; i0s[slot][lt] = sp * n0;
    r1s[slot][lt] = cp * n1; i1s[slot][lt] = sp * n1;
    __syncthreads();

    {
        int mod = lt >> 5;
        int uu = lt & 31;
        const float* R = mod ? r1s[slot] : r0s[slot];
        const float* I = mod ? i1s[slot] : i0s[slot];
        float pr = 0.f, pi = 0.f;
        #pragma unroll 16
        for (int e = 0; e < Ee; e++) {
            float kr = krT[e * Uu + uu];
            float ki = kiT[e * Uu + uu];
            float rr = R[e], im = I[e];
            pr += kr * rr - ki * im;
            pi += ki * rr + kr * im;
        }
        ms[slot][lt] = pr * pr + pi * pi;
    }
    __syncthreads();

    {
        int cc = lt;
        float acc = b1[cc];
        #pragma unroll 16
        for (int k = 0; k < CELL; k++) acc += ms[slot][k] * W1s[cc * 65 + k];
        hids[slot][cc] = fmaxf(acc, 0.f);
    }
    __syncthreads();

    if (lt < Cc) {
        float acc = b2[lt];
        const float* w2 = W2 + lt * CELL;
        #pragma unroll 16
        for (int k = 0; k < CELL; k++) acc += hids[slot][k] * w2[k];
        preds[slot][lt] = tanhf(acc);
    }
    __syncthreads();

    if (lt == 0) {
        float m = preds[slot][0];
        #pragma unroll
        for (int k = 1; k < Cc; k++) m = fmaxf(m, preds[slot][k]);
        float se = 0.f;
        #pragma unroll
        for (int k = 0; k < Cc; k++) se += expf(preds[slot][k] - m);
        lse_s[slot] = m + logf(se);
    }
    __syncthreads();

    if (lt < Cc) out[row * Cc + lt] = preds[slot][lt] - lse_s[slot];
}

// ---------------------------------------------------------------------------
extern "C" void kernel_launch(void* const* d_in, const int* in_sizes, int n_in,
                              void* d_out, int out_size) {
    const float* x0        = (const float*)d_in[0];
    const float* x1        = (const float*)d_in[1];
    const float* smask     = (const float*)d_in[2];
    const float* umask     = (const float*)d_in[3];
    const float* W_ih0     = (const float*)d_in[4];
    const float* W_hh0     = (const float*)d_in[5];
    const float* b_ih0     = (const float*)d_in[6];
    const float* b_hh0     = (const float*)d_in[7];
    const float* W_ih1     = (const float*)d_in[8];
    const float* W_hh1     = (const float*)d_in[9];
    const float* b_ih1     = (const float*)d_in[10];
    const float* b_hh1     = (const float*)d_in[11];
    const float* phase_tab = (const float*)d_in[12];
    const float* meas_k    = (const float*)d_in[13];
    const float* W1        = (const float*)d_in[14];
    const float* b1        = (const float*)d_in[15];
    const float* W2        = (const float*)d_in[16];
    const float* b2        = (const float*)d_in[17];
    float* out = (float*)d_out;

    dim3 ggrid(5, ROWS / 64, 2);
    gemm_xproj<<<ggrid, 256>>>(x0, W_ih0, b_ih0, b_hh0,
                               x1, W_ih1, b_ih1, b_hh1, umask, meas_k);

    lstm_kernel<<<64, 256>>>(W_hh0, W_hh1);

    epilogue_kernel<<<ROWS / 4, 256>>>(smask, phase_tab, W1, b1, W2, b2, out);
}

// round 3
// speedup vs baseline: 1.2290x; 1.1524x over previous
#include <cuda_runtime.h>
#include <math.h>
#include <stdint.h>

// Problem constants
#define Bb 32
#define Tt 64
#define Ee 64
#define Uu 32
#define D0 300
#define D1 100
#define Ss 9
#define CELL 64
#define Cc 6
#define ROWS (Bb*Tt)      // 2048
#define G4E (4*Ee)        // 256

// Device scratch
__device__ float g_xproj0[ROWS * G4E];
__device__ float g_xproj1[ROWS * G4E];
__device__ float g_h0[ROWS * Ee];
__device__ float g_h1[ROWS * Ee];
__device__ float g_krT[Ee * Uu];   // [e][u]
__device__ float g_kiT[Ee * Uu];

// ---------------------------------------------------------------------------
// fast activations (MUFU-based, clamped)
// ---------------------------------------------------------------------------
__device__ __forceinline__ float fsig(float x) {
    x = fminf(fmaxf(x, -30.f), 30.f);
    return __fdividef(1.f, 1.f + __expf(-x));
}
__device__ __forceinline__ float ftanh_(float x) {
    x = fminf(fmaxf(x, -15.f), 15.f);
    float e = __expf(2.f * x);
    return 1.f - __fdividef(2.f, e + 1.f);
}

// packed f32x2 helpers (Blackwell)
__device__ __forceinline__ unsigned long long ffma2(unsigned long long a,
                                                    unsigned long long b,
                                                    unsigned long long c) {
    unsigned long long d;
    asm("fma.rn.f32x2 %0, %1, %2, %3;" : "=l"(d) : "l"(a), "l"(b), "l"(c));
    return d;
}
__device__ __forceinline__ unsigned long long fadd2(unsigned long long a,
                                                    unsigned long long b) {
    unsigned long long d;
    asm("add.rn.f32x2 %0, %1, %2;" : "=l"(d) : "l"(a), "l"(b));
    return d;
}

// ---------------------------------------------------------------------------
// Kernel 1: merged input-projection GEMM (both modalities) + prep slice.
// grid = (5, 64, 2): x in [0,4) -> 64-wide N tiles; x==4,y==0,z==0 -> prep.
// Tiles: BM=32, BN=64, BK=16. 256 threads, 2x4 microtile.
// Double-buffered smem, register prefetch, one barrier per K-tile.
// out[m][n] = umask[m]*sum_k A[m][k]*W[n][k] + bih[n] + bhh[n]
// ---------------------------------------------------------------------------
__global__ void __launch_bounds__(256) gemm_xproj(
    const float* __restrict__ x0, const float* __restrict__ Wih0,
    const float* __restrict__ bih0, const float* __restrict__ bhh0,
    const float* __restrict__ x1, const float* __restrict__ Wih1,
    const float* __restrict__ bih1, const float* __restrict__ bhh1,
    const float* __restrict__ umask, const float* __restrict__ mk) {

    if (blockIdx.x == 4) {
        if (blockIdx.y != 0 || blockIdx.z != 0) return;
        // prep: normalize measurement kernel, store transposed
        __shared__ float inv_norm[Uu];
        int tid = threadIdx.x;
        if (tid < Uu) {
            float s = 0.f;
            const float* p = mk + tid * (Ee * 2);
            #pragma unroll 8
            for (int i = 0; i < Ee * 2; i++) s += p[i] * p[i];
            inv_norm[tid] = 1.f / fmaxf(sqrtf(s), 1e-12f);
        }
        __syncthreads();
        for (int idx = tid; idx < Uu * Ee; idx += blockDim.x) {
            int u = idx >> 6;
            int e = idx & 63;
            float inv = inv_norm[u];
            g_krT[e * Uu + u] = mk[(u * Ee + e) * 2 + 0] * inv;
            g_kiT[e * Uu + u] = mk[(u * Ee + e) * 2 + 1] * inv;
        }
        return;
    }

    int mod = blockIdx.z;
    const float* A   = mod ? x1 : x0;
    const float* W   = mod ? Wih1 : Wih0;
    const float* bih = mod ? bih1 : bih0;
    const float* bhh = mod ? bhh1 : bhh0;
    float* out = mod ? g_xproj1 : g_xproj0;
    const int K = mod ? D1 : D0;

    // padded, double-buffered tiles
    __shared__ __align__(16) float As[2][16][34];   // [buf][k][m], pad 2
    __shared__ __align__(16) float Ws[2][16][68];   // [buf][k][n], pad 4

    int tid = threadIdx.x;
    int lk = tid & 15;          // k within tile
    int lm = tid >> 4;          // 0..15
    int bm = blockIdx.y * 32, bn = blockIdx.x * 64;

    const float* Ar0 = A + (size_t)(bm + lm) * K;
    const float* Ar1 = Ar0 + (size_t)16 * K;
    const float* Wr0 = W + (size_t)(bn + lm) * K;
    const float* Wr1 = Wr0 + (size_t)16 * K;
    const float* Wr2 = Wr0 + (size_t)32 * K;
    const float* Wr3 = Wr0 + (size_t)48 * K;

    const int ntiles = (K + 15) >> 4;

    // prologue: tile 0 (k = lk always < K since K >= 100)
    float a0 = Ar0[lk], a1 = Ar1[lk];
    float w0 = Wr0[lk], w1 = Wr1[lk], w2 = Wr2[lk], w3 = Wr3[lk];
    As[0][lk][lm] = a0;  As[0][lk][lm + 16] = a1;
    Ws[0][lk][lm] = w0;  Ws[0][lk][lm + 16] = w1;
    Ws[0][lk][lm + 32] = w2;  Ws[0][lk][lm + 48] = w3;
    __syncthreads();

    float acc[2][4] = {};
    int tx = tid & 15;          // n-quad
    int ty = tid >> 4;          // m-pair

    for (int tl = 0; tl < ntiles; tl++) {
        int cur = tl & 1;
        bool has = (tl + 1) < ntiles;
        if (has) {
            int k = (tl + 1) * 16 + lk;
            bool v = k < K;
            a0 = v ? Ar0[k] : 0.f;  a1 = v ? Ar1[k] : 0.f;
            w0 = v ? Wr0[k] : 0.f;  w1 = v ? Wr1[k] : 0.f;
            w2 = v ? Wr2[k] : 0.f;  w3 = v ? Wr3[k] : 0.f;
        }
        #pragma unroll
        for (int kk = 0; kk < 16; kk++) {
            float2 av = *(const float2*)&As[cur][kk][ty * 2];
            float4 wv = *(const float4*)&Ws[cur][kk][tx * 4];
            acc[0][0] += av.x * wv.x;  acc[0][1] += av.x * wv.y;
            acc[0][2] += av.x * wv.z;  acc[0][3] += av.x * wv.w;
            acc[1][0] += av.y * wv.x;  acc[1][1] += av.y * wv.y;
            acc[1][2] += av.y * wv.z;  acc[1][3] += av.y * wv.w;
        }
        if (has) {
            int nb = cur ^ 1;
            As[nb][lk][lm] = a0;  As[nb][lk][lm + 16] = a1;
            Ws[nb][lk][lm] = w0;  Ws[nb][lk][lm + 16] = w1;
            Ws[nb][lk][lm + 32] = w2;  Ws[nb][lk][lm + 48] = w3;
        }
        __syncthreads();
    }

    int n = bn + tx * 4;
    float bv0 = bih[n + 0] + bhh[n + 0];
    float bv1 = bih[n + 1] + bhh[n + 1];
    float bv2 = bih[n + 2] + bhh[n + 2];
    float bv3 = bih[n + 3] + bhh[n + 3];
    #pragma unroll
    for (int i = 0; i < 2; i++) {
        int m = bm + ty * 2 + i;
        float um = umask[m];
        float4 o;
        o.x = um * acc[i][0] + bv0;
        o.y = um * acc[i][1] + bv1;
        o.z = um * acc[i][2] + bv2;
        o.w = um * acc[i][3] + bv3;
        *(float4*)&out[(size_t)m * G4E + n] = o;
    }
}

// ---------------------------------------------------------------------------
// Kernel 2: LSTM recurrence (unchanged from R2 — shuffle gather, double-buffer
// h, single barrier per step, prefetched xp, packed f32x2 dot).
// ---------------------------------------------------------------------------
__global__ void __launch_bounds__(256, 1) lstm_kernel(
    const float* __restrict__ Whh0, const float* __restrict__ Whh1) {
    int mod = blockIdx.x >> 5;
    int b = blockIdx.x & 31;
    const float* Whh = mod ? Whh1 : Whh0;
    const float* xp = (mod ? g_xproj1 : g_xproj0) + (size_t)b * Tt * G4E;
    float* hout = (mod ? g_h1 : g_h0) + (size_t)b * Tt * Ee;

    int tid = threadIdx.x;
    int w = tid >> 5, l = tid & 31;
    int gt = l & 3;
    int cell = w * 8 + (l >> 2);
    int r = gt * 64 + cell;

    unsigned long long wp[32];
    {
        const float2* src = (const float2*)(Whh + (size_t)r * Ee);
        #pragma unroll
        for (int i = 0; i < 32; i++) {
            union { float2 f; unsigned long long u; } cv;
            cv.f = src[i];
            wp[i] = cv.u;
        }
    }

    __shared__ __align__(16) float hs[2][Ee];
    if (tid < Ee) hs[0][tid] = 0.f;
    float c = 0.f;
    __syncthreads();

    float gpre = xp[r];
    #pragma unroll 1
    for (int t = 0; t < Tt; t++) {
        float gnext = (t + 1 < Tt) ? xp[(t + 1) * G4E + r] : 0.f;

        const ulonglong2* h2 = (const ulonglong2*)hs[t & 1];
        unsigned long long a0 = 0ull, a1 = 0ull, a2 = 0ull, a3 = 0ull;
        #pragma unroll
        for (int i = 0; i < 16; i += 2) {
            ulonglong2 hv = h2[i];
            a0 = ffma2(wp[2 * i + 0], hv.x, a0);
            a1 = ffma2(wp[2 * i + 1], hv.y, a1);
            ulonglong2 hv2 = h2[i + 1];
            a2 = ffma2(wp[2 * i + 2], hv2.x, a2);
            a3 = ffma2(wp[2 * i + 3], hv2.y, a3);
        }
        unsigned long long s = fadd2(fadd2(a0, a1), fadd2(a2, a3));
        float lo, hi;
        asm("mov.b64 {%0,%1}, %2;" : "=f"(lo), "=f"(hi) : "l"(s));
        float g = gpre + lo + hi;
        gpre = gnext;

        float act = (gt == 2) ? ftanh_(g) : fsig(g);

        float v1 = __shfl_xor_sync(0xffffffffu, act, 1);
        float v2 = __shfl_xor_sync(0xffffffffu, act, 2);
        float v3 = __shfl_xor_sync(0xffffffffu, v1, 2);

        if (gt == 0) {
            c = v1 * c + act * v2;
            float h = ftanh_(v3 * ftanh_(c));
            hs[(t + 1) & 1][cell] = h;
            hout[t * Ee + cell] = h;
        }
        __syncthreads();
    }
}

// ---------------------------------------------------------------------------
// Kernel 3: normalize + phase + measurement + MLP + log_softmax.
// ---------------------------------------------------------------------------
__global__ void __launch_bounds__(256) epilogue_kernel(
    const float* __restrict__ smask, const float* __restrict__ phase_table,
    const float* __restrict__ W1, const float* __restrict__ b1,
    const float* __restrict__ W2, const float* __restrict__ b2,
    float* __restrict__ out) {
    __shared__ float krT[Ee * Uu];
    __shared__ float kiT[Ee * Uu];
    __shared__ float W1s[CELL * 65];
    __shared__ float r0s[4][Ee], i0s[4][Ee], r1s[4][Ee], i1s[4][Ee];
    __shared__ float ms[4][2 * Uu];
    __shared__ float hids[4][CELL];
    __shared__ float preds[4][8];
    __shared__ float part[4][2][2];
    __shared__ int sidx[4];
    __shared__ float lse_s[4];

    int tid = threadIdx.x;
    int slot = tid >> 6;
    int lt = tid & 63;
    int row = blockIdx.x * 4 + slot;

    for (int i = tid; i < Ee * Uu; i += 256) { krT[i] = g_krT[i]; kiT[i] = g_kiT[i]; }
    for (int i = tid; i < CELL * CELL; i += 256) {
        int cc = i >> 6, k = i & 63;
        W1s[cc * 65 + k] = W1[i];
    }

    float h0 = g_h0[row * Ee + lt];
    float h1 = g_h1[row * Ee + lt];
    float v0 = h0 * h0, v1 = h1 * h1;
    #pragma unroll
    for (int off = 16; off; off >>= 1) {
        v0 += __shfl_xor_sync(0xffffffffu, v0, off);
        v1 += __shfl_xor_sync(0xffffffffu, v1, off);
    }
    if ((tid & 31) == 0) { part[slot][lt >> 5][0] = v0; part[slot][lt >> 5][1] = v1; }
    if (lt == 0) {
        const float* sm = smask + row * Ss;
        float best = sm[0]; int bi = 0;
        #pragma unroll
        for (int e = 1; e < Ss; e++) { float v = sm[e]; if (v > best) { best = v; bi = e; } }
        sidx[slot] = bi;
    }
    __syncthreads();

    float s0 = part[slot][0][0] + part[slot][1][0];
    float s1 = part[slot][0][1] + part[slot][1][1];
    float inv0 = 1.f / fmaxf(sqrtf(s0), 1e-12f);
    float inv1 = 1.f / fmaxf(sqrtf(s1), 1e-12f);
    float n0 = h0 * inv0, n1 = h1 * inv1;

    float ph = phase_table[sidx[slot] * Ee + lt];
    float cp = cosf(ph), sp = sinf(ph);
    r0s[slot][lt] = cp * n0; i0s[slot][lt] = sp * n0;
    r1s[slot][lt] = cp * n1; i1s[slot][lt] = sp * n1;
    __syncthreads();

    {
        int mod = lt >> 5;
        int uu = lt & 31;
        const float* R = mod ? r1s[slot] : r0s[slot];
        const float* I = mod ? i1s[slot] : i0s[slot];
        float pr = 0.f, pi = 0.f;
        #pragma unroll 16
        for (int e = 0; e < Ee; e++) {
            float kr = krT[e * Uu + uu];
            float ki = kiT[e * Uu + uu];
            float rr = R[e], im = I[e];
            pr += kr * rr - ki * im;
            pi += ki * rr + kr * im;
        }
        ms[slot][lt] = pr * pr + pi * pi;
    }
    __syncthreads();

    {
        int cc = lt;
        float acc = b1[cc];
        #pragma unroll 16
        for (int k = 0; k < CELL; k++) acc += ms[slot][k] * W1s[cc * 65 + k];
        hids[slot][cc] = fmaxf(acc, 0.f);
    }
    __syncthreads();

    if (lt < Cc) {
        float acc = b2[lt];
        const float* w2 = W2 + lt * CELL;
        #pragma unroll 16
        for (int k = 0; k < CELL; k++) acc += hids[slot][k] * w2[k];
        preds[slot][lt] = tanhf(acc);
    }
    __syncthreads();

    if (lt == 0) {
        float m = preds[slot][0];
        #pragma unroll
        for (int k = 1; k < Cc; k++) m = fmaxf(m, preds[slot][k]);
        float se = 0.f;
        #pragma unroll
        for (int k = 0; k < Cc; k++) se += expf(preds[slot][k] - m);
        lse_s[slot] = m + logf(se);
    }
    __syncthreads();

    if (lt < Cc) out[row * Cc + lt] = preds[slot][lt] - lse_s[slot];
}

// ---------------------------------------------------------------------------
extern "C" void kernel_launch(void* const* d_in, const int* in_sizes, int n_in,
                              void* d_out, int out_size) {
    const float* x0        = (const float*)d_in[0];
    const float* x1        = (const float*)d_in[1];
    const float* smask     = (const float*)d_in[2];
    const float* umask     = (const float*)d_in[3];
    const float* W_ih0     = (const float*)d_in[4];
    const float* W_hh0     = (const float*)d_in[5];
    const float* b_ih0     = (const float*)d_in[6];
    const float* b_hh0     = (const float*)d_in[7];
    const float* W_ih1     = (const float*)d_in[8];
    const float* W_hh1     = (const float*)d_in[9];
    const float* b_ih1     = (const float*)d_in[10];
    const float* b_hh1     = (const float*)d_in[11];
    const float* phase_tab = (const float*)d_in[12];
    const float* meas_k    = (const float*)d_in[13];
    const float* W1        = (const float*)d_in[14];
    const float* b1        = (const float*)d_in[15];
    const float* W2        = (const float*)d_in[16];
    const float* b2        = (const float*)d_in[17];
    float* out = (float*)d_out;

    dim3 ggrid(5, ROWS / 32, 2);   // (5, 64, 2)
    gemm_xproj<<<ggrid, 256>>>(x0, W_ih0, b_ih0, b_hh0,
                               x1, W_ih1, b_ih1, b_hh1, umask, meas_k);

    lstm_kernel<<<64, 256>>>(W_hh0, W_hh1);

    epilogue_kernel<<<ROWS / 4, 256>>>(smask, phase_tab, W1, b1, W2, b2, out);
}